// round 5
// baseline (speedup 1.0000x reference)
#include <cuda_runtime.h>

// DistMult edge scoring, R5 (= R4 resubmit after infra failure):
//   out[e] = sigmoid( sum_d h[src[e]][d] * W[rel[e]][d] * h[dst[e]][d] )
// h: [100000,128] f32 (L2-resident), W: [6,128] f32, src/dst/rel: int32.
//
// L1-wavefront-optimized layout:
//   - 2 edges per warp (16 lanes each): 4-step shuffle reduce serves both
//     edges -> 2 shuffle wavefronts/edge instead of 5.
//   - W cached in registers (6 rels x 2 float4 per lane), selected by a
//     half-warp-uniform switch -> removes 4 LDS wavefronts/edge.
//   - Each lane loads float4 [sub] and [sub+16] of its row: both LDG.128
//     fully coalesced (256B contiguous per half-warp).
//   - Paired index loads / output stores share sectors.

#define WPB 8
#define TPB (WPB * 32)
#define GRID_BLOCKS (148 * 8)

__device__ __forceinline__ float edge_score(const float4* __restrict__ h4,
                                            const float4* wlo, const float4* whi,
                                            int s, int d, int r, int sub)
{
    const float4* __restrict__ up = h4 + s * 32;
    const float4* __restrict__ vp = h4 + d * 32;
    float4 u0 = __ldg(up + sub);
    float4 u1 = __ldg(up + 16 + sub);
    float4 v0 = __ldg(vp + sub);
    float4 v1 = __ldg(vp + 16 + sub);

    // r is uniform within each half-warp -> at most 2 of 6 cases execute.
    float4 wl, wh;
    switch (r) {
        case 0:  wl = wlo[0]; wh = whi[0]; break;
        case 1:  wl = wlo[1]; wh = whi[1]; break;
        case 2:  wl = wlo[2]; wh = whi[2]; break;
        case 3:  wl = wlo[3]; wh = whi[3]; break;
        case 4:  wl = wlo[4]; wh = whi[4]; break;
        default: wl = wlo[5]; wh = whi[5]; break;
    }

    float sum = u0.x * wl.x * v0.x
              + u0.y * wl.y * v0.y
              + u0.z * wl.z * v0.z
              + u0.w * wl.w * v0.w
              + u1.x * wh.x * v1.x
              + u1.y * wh.y * v1.y
              + u1.z * wh.z * v1.z
              + u1.w * wh.w * v1.w;

    #pragma unroll
    for (int off = 8; off > 0; off >>= 1)
        sum += __shfl_xor_sync(0xffffffffu, sum, off);
    return sum;
}

__global__ __launch_bounds__(TPB)
void distmult_kernel(const float* __restrict__ h,
                     const float* __restrict__ W,
                     const int* __restrict__ src,
                     const int* __restrict__ dst,
                     const int* __restrict__ rel,
                     float* __restrict__ out,
                     int E)
{
    const int lane = threadIdx.x & 31;
    const int sub  = lane & 15;   // lane within half-warp
    const int half = lane >> 4;   // which edge of the pair

    // Register-resident W: this lane's two dim-chunks for all 6 relations.
    const float4* __restrict__ W4 = reinterpret_cast<const float4*>(W);
    float4 wlo[6], whi[6];
    #pragma unroll
    for (int i = 0; i < 6; i++) {
        wlo[i] = __ldg(W4 + i * 32 + sub);
        whi[i] = __ldg(W4 + i * 32 + 16 + sub);
    }

    const float4* __restrict__ h4 = reinterpret_cast<const float4*>(h);

    const int warp_glb    = blockIdx.x * WPB + (threadIdx.x >> 5);
    const int warp_step   = gridDim.x * WPB;
    const int npairs_full = E >> 1;       // pairs with both edges valid

    for (int p = warp_glb; p < npairs_full; p += warp_step) {
        int e = 2 * p + half;
        int s = __ldg(src + e);
        int d = __ldg(dst + e);
        int r = __ldg(rel + e);
        float sum = edge_score(h4, wlo, whi, s, d, r, sub);
        if (sub == 0)
            out[e] = 1.0f / (1.0f + __expf(-sum));
    }

    // Odd-E tail: one leftover edge handled by the first warp, half 0.
    if ((E & 1) && warp_glb == 0 && half == 0) {
        int e = E - 1;
        int s = __ldg(src + e);
        int d = __ldg(dst + e);
        int r = __ldg(rel + e);
        float sum = edge_score(h4, wlo, whi, s, d, r, sub);
        if (sub == 0)
            out[e] = 1.0f / (1.0f + __expf(-sum));
    }
}

extern "C" void kernel_launch(void* const* d_in, const int* in_sizes, int n_in,
                              void* d_out, int out_size)
{
    const float* h   = (const float*)d_in[0];
    const float* W   = (const float*)d_in[1];
    const int*   src = (const int*)d_in[2];
    const int*   dst = (const int*)d_in[3];
    const int*   rel = (const int*)d_in[4];
    float* out = (float*)d_out;

    int E = in_sizes[2];

    int npairs = (E + 1) >> 1;
    int blocks_needed = (npairs + WPB - 1) / WPB;
    if (blocks_needed < 1) blocks_needed = 1;
    int blocks = blocks_needed < GRID_BLOCKS ? blocks_needed : GRID_BLOCKS;
    distmult_kernel<<<blocks, TPB>>>(h, W, src, dst, rel, out, E);
}

// round 6
// speedup vs baseline: 2.0856x; 2.0856x over previous
#include <cuda_runtime.h>

// DistMult edge scoring, R6:
//   out[e] = sigmoid( sum_d h[src[e]][d] * W[rel[e]][d] * h[dst[e]][d] )
// h: [100000,128] f32 (L2-resident), W: [6,128] f32 (L1-resident), idx int32.
//
// Pair scheme (2 edges/warp, 16 lanes each) WITHOUT the register W cache:
//   - shuffles: 4 steps serve 2 edges -> 2 wf/edge (vs 5 at 32-lane)
//   - W fetched per-edge via __ldg: 3KB table lives in L1 -> hit, 0 regs
//   - paired index loads / stores share sectors
//   - regs ~44 -> occupancy back near full, latency hidden again
// L1 wavefronts/edge ~= 8 (u,v) + 4 (W) + 1.5 (idx) + 0.25 (stg) = 13.75.

#define WPB 8
#define TPB (WPB * 32)
#define GRID_BLOCKS (148 * 8)

__device__ __forceinline__ float edge_score(const float4* __restrict__ h4,
                                            const float4* __restrict__ W4,
                                            int s, int d, int r, int sub)
{
    const float4* __restrict__ up = h4 + s * 32;
    const float4* __restrict__ vp = h4 + d * 32;
    const float4* __restrict__ wp = W4 + r * 32;

    float4 u0 = __ldg(up + sub);
    float4 v0 = __ldg(vp + sub);
    float4 wl = __ldg(wp + sub);
    float4 u1 = __ldg(up + 16 + sub);
    float4 v1 = __ldg(vp + 16 + sub);
    float4 wh = __ldg(wp + 16 + sub);

    float sum = u0.x * wl.x * v0.x
              + u0.y * wl.y * v0.y
              + u0.z * wl.z * v0.z
              + u0.w * wl.w * v0.w
              + u1.x * wh.x * v1.x
              + u1.y * wh.y * v1.y
              + u1.z * wh.z * v1.z
              + u1.w * wh.w * v1.w;

    #pragma unroll
    for (int off = 8; off > 0; off >>= 1)
        sum += __shfl_xor_sync(0xffffffffu, sum, off);
    return sum;
}

__global__ __launch_bounds__(TPB)
void distmult_kernel(const float* __restrict__ h,
                     const float* __restrict__ W,
                     const int* __restrict__ src,
                     const int* __restrict__ dst,
                     const int* __restrict__ rel,
                     float* __restrict__ out,
                     int E)
{
    const int lane = threadIdx.x & 31;
    const int sub  = lane & 15;   // lane within half-warp
    const int half = lane >> 4;   // which edge of the pair

    const float4* __restrict__ h4 = reinterpret_cast<const float4*>(h);
    const float4* __restrict__ W4 = reinterpret_cast<const float4*>(W);

    const int warp_glb    = blockIdx.x * WPB + (threadIdx.x >> 5);
    const int warp_step   = gridDim.x * WPB;
    const int npairs_full = E >> 1;

    for (int p = warp_glb; p < npairs_full; p += warp_step) {
        int e = 2 * p + half;
        int s = __ldg(src + e);
        int d = __ldg(dst + e);
        int r = __ldg(rel + e);
        float sum = edge_score(h4, W4, s, d, r, sub);
        if (sub == 0)
            out[e] = 1.0f / (1.0f + __expf(-sum));
    }

    // Odd-E tail: one leftover edge handled by the first warp's half 0.
    if ((E & 1) && warp_glb == 0 && half == 0) {
        int e = E - 1;
        int s = __ldg(src + e);
        int d = __ldg(dst + e);
        int r = __ldg(rel + e);
        float sum = edge_score(h4, W4, s, d, r, sub);
        if (sub == 0)
            out[e] = 1.0f / (1.0f + __expf(-sum));
    }
}

extern "C" void kernel_launch(void* const* d_in, const int* in_sizes, int n_in,
                              void* d_out, int out_size)
{
    const float* h   = (const float*)d_in[0];
    const float* W   = (const float*)d_in[1];
    const int*   src = (const int*)d_in[2];
    const int*   dst = (const int*)d_in[3];
    const int*   rel = (const int*)d_in[4];
    float* out = (float*)d_out;

    int E = in_sizes[2];

    int npairs = (E + 1) >> 1;
    int blocks_needed = (npairs + WPB - 1) / WPB;
    if (blocks_needed < 1) blocks_needed = 1;
    int blocks = blocks_needed < GRID_BLOCKS ? blocks_needed : GRID_BLOCKS;
    distmult_kernel<<<blocks, TPB>>>(h, W, src, dst, rel, out, E);
}